// round 13
// baseline (speedup 1.0000x reference)
#include <cuda_runtime.h>
#include <math.h>
#include <stdint.h>

// Problem constants (fixed shapes)
#define BB   16
#define LL   2048
#define HH   1024
#define SS   32
#define PP   256
#define NN   512            // 2*P combined GEMM width (a | s)
#define MM   (BB*LL)        // 32768 rows
#define NASP 8
#define NRAT 5

// Output layout: (result[B,8,5], outputs[B,L,H], aspect_doc[B,32,9]) flattened
#define OFF_RESULT 0
#define OFF_X      640
#define OFF_ASP    (640 + BB*LL*HH)

// -------- device scratch (static; no runtime allocation allowed) --------
__device__ float g_Wc[HH * NN];            // folded, tf32-rounded weights (k-major)
__device__ float g_Xt[(size_t)MM * HH];    // tf32-rounded copy of X (A operand)
__device__ float g_colsum[NN];             // sum_h s_h*W[h,n]
__device__ float g_bw[NN];                 // sum_h b_h*W[h,n]
__device__ float g_mu[MM];
__device__ float g_rstd[MM];
__device__ int   g_seg[MM];                // segment id per row, -1 = excluded
__device__ int   g_pi[BB * SS];            // boundary positions
__device__ float g_segsum[BB * SS * NN];

// ===================== K0: fold LN scale/bias into weights =====================
__global__ void prep_kernel(const float* __restrict__ Wa, const float* __restrict__ Ws,
                            const float* __restrict__ sa, const float* __restrict__ ba,
                            const float* __restrict__ ss, const float* __restrict__ bs) {
    int n = blockIdx.x;           // 0..511
    int t = threadIdx.x;          // 256
    bool isA = (n < PP);
    const float* W  = isA ? Wa : Ws;
    const float* sv = isA ? sa : ss;
    const float* bv = isA ? ba : bs;
    int nc = isA ? n : (n - PP);
    float cs = 0.f, bw = 0.f;
    for (int k = t; k < HH; k += 256) {
        float w = W[k * PP + nc];
        float f = sv[k] * w;
        unsigned u;
        asm("cvt.rna.tf32.f32 %0, %1;" : "=r"(u) : "f"(f));
        g_Wc[k * NN + n] = __uint_as_float(u);
        cs += f;
        bw += bv[k] * w;
    }
    __shared__ float r1[256], r2[256];
    r1[t] = cs; r2[t] = bw;
    __syncthreads();
    for (int o = 128; o > 0; o >>= 1) {
        if (t < o) { r1[t] += r1[t + o]; r2[t] += r2[t + o]; }
        __syncthreads();
    }
    if (t == 0) { g_colsum[n] = r1[0]; g_bw[n] = r2[0]; }
}

// ===== K1: per-row mean/rstd + passthrough copy + tf32-rounded A operand =====
__global__ void rowstats_copy_kernel(const float* __restrict__ X, float* __restrict__ outX) {
    int row = blockIdx.x;
    int t = threadIdx.x;          // 256, one float4 each
    float4 v = ((const float4*)X)[(size_t)row * 256 + t];
    ((float4*)outX)[(size_t)row * 256 + t] = v;
    // tf32 round-to-nearest copy for the GEMM A operand
    unsigned u0, u1, u2, u3;
    asm("cvt.rna.tf32.f32 %0, %1;" : "=r"(u0) : "f"(v.x));
    asm("cvt.rna.tf32.f32 %0, %1;" : "=r"(u1) : "f"(v.y));
    asm("cvt.rna.tf32.f32 %0, %1;" : "=r"(u2) : "f"(v.z));
    asm("cvt.rna.tf32.f32 %0, %1;" : "=r"(u3) : "f"(v.w));
    float4 w = make_float4(__uint_as_float(u0), __uint_as_float(u1),
                           __uint_as_float(u2), __uint_as_float(u3));
    ((float4*)g_Xt)[(size_t)row * 256 + t] = w;

    float s = v.x + v.y + v.z + v.w;
    float q = v.x * v.x + v.y * v.y + v.z * v.z + v.w * v.w;
    for (int o = 16; o > 0; o >>= 1) {
        s += __shfl_down_sync(0xffffffffu, s, o);
        q += __shfl_down_sync(0xffffffffu, q, o);
    }
    __shared__ float wsm[8], wqm[8];
    if ((t & 31) == 0) { wsm[t >> 5] = s; wqm[t >> 5] = q; }
    __syncthreads();
    if (t == 0) {
        float S = 0.f, Q = 0.f;
        for (int i = 0; i < 8; i++) { S += wsm[i]; Q += wqm[i]; }
        float mu = S * (1.0f / HH);
        float var = Q * (1.0f / HH) - mu * mu;
        g_mu[row] = mu;
        g_rstd[row] = rsqrtf(var + 1e-5f);
    }
}

// ===================== K2: segment id per row + boundary positions =====================
__global__ void seg_kernel(const int* __restrict__ p) {
    int b = blockIdx.x;
    int t = threadIdx.x;          // 256 threads, 8 positions each
    const int* pb = p + b * LL;
    int base = t * 8;
    int cnt = 0;
#pragma unroll
    for (int i = 0; i < 8; i++) cnt += (pb[base + i] > 0);
    __shared__ int sc[256];
    sc[t] = cnt;
    __syncthreads();
    for (int o = 1; o < 256; o <<= 1) {
        int v = (t >= o) ? sc[t - o] : 0;
        __syncthreads();
        sc[t] += v;
        __syncthreads();
    }
    int k = (t > 0) ? sc[t - 1] : 0;  // exclusive prefix: boundaries before chunk
#pragma unroll
    for (int i = 0; i < 8; i++) {
        int pos = base + i;
        if (pb[pos] > 0) {
            if (k < SS) g_pi[b * SS + k] = pos;
            g_seg[b * LL + pos] = -1;     // boundary row excluded
            k++;
        } else {
            g_seg[b * LL + pos] = (k < SS) ? k : -1;
        }
    }
}

// ===================== K2b: zero the segment-sum accumulator (graph-replay safe) ==========
__global__ void zero_segsum_kernel() {
    int i = blockIdx.x * 256 + threadIdx.x;   // 65536 float4 = 262144 floats
    ((float4*)g_segsum)[i] = make_float4(0.f, 0.f, 0.f, 0.f);
}

// ===================== K3: tf32 mma.sync GEMM 128x256 tile, cp.async 2-stage =====
// + fused LN/GELU/segmented-sum epilogue
#define A_STRIDE 36
#define B_STRIDE 260
#define SMEM_FLOATS (2 * (128 * A_STRIDE) + 2 * (32 * B_STRIDE))
#define SMEM_BYTES  (SMEM_FLOATS * 4)      // 103424 bytes

__global__ void __launch_bounds__(256, 1) gemm_kernel(const float* __restrict__ Xt) {
    extern __shared__ float smem[];
    float (*As)[128][A_STRIDE] = (float (*)[128][A_STRIDE])smem;
    float (*Bs)[32][B_STRIDE]  = (float (*)[32][B_STRIDE])(smem + 2 * 128 * A_STRIDE);

    int tid = threadIdx.x;
    int lane = tid & 31, wid = tid >> 5;
    int wm = wid & 1, wn = wid >> 1;       // 2 warps (M, 64 rows) x 4 warps (N, 64 cols)
    int bm = blockIdx.y * 128;
    int bn = blockIdx.x * 256;

    // per-thread load coordinates (fixed across tiles)
    int a_row = tid >> 3;            // 0..31 (stepped by 32 over j)
    int a_col = (tid & 7) * 4;       // 0,4,...,28
    int b_kr  = tid >> 6;            // 0..3 (stepped by 4 over j)
    int b_nc  = (tid & 63) * 4;      // 0..252

    const float* a_base = Xt + (size_t)(bm + a_row) * HH + a_col;
    const float* b_base = g_Wc + (size_t)b_kr * NN + bn + b_nc;

    float c[4][8][4];
#pragma unroll
    for (int i = 0; i < 4; i++)
#pragma unroll
        for (int j = 0; j < 8; j++)
#pragma unroll
            for (int r = 0; r < 4; r++) c[i][j][r] = 0.f;

#define LOAD_TILE(KT, BUF)                                                          \
    do {                                                                            \
        _Pragma("unroll")                                                           \
        for (int j = 0; j < 4; j++) {   /* A: 128x32 = 1024 float4 */               \
            unsigned dst = (unsigned)__cvta_generic_to_shared(                      \
                &As[BUF][j * 32 + a_row][a_col]);                                   \
            const float* src = a_base + (size_t)(j * 32) * HH + (KT);               \
            asm volatile("cp.async.cg.shared.global [%0], [%1], 16;"                \
                         :: "r"(dst), "l"(src) : "memory");                         \
        }                                                                           \
        _Pragma("unroll")                                                           \
        for (int j = 0; j < 8; j++) {   /* B: 32x256 = 2048 float4 */               \
            unsigned dst = (unsigned)__cvta_generic_to_shared(                      \
                &Bs[BUF][j * 4 + b_kr][b_nc]);                                      \
            const float* src = b_base + (size_t)((KT) + j * 4) * NN;                \
            asm volatile("cp.async.cg.shared.global [%0], [%1], 16;"                \
                         :: "r"(dst), "l"(src) : "memory");                         \
        }                                                                           \
        asm volatile("cp.async.commit_group;" ::: "memory");                        \
    } while (0)

    LOAD_TILE(0, 0);
    LOAD_TILE(32, 1);

    for (int kt = 0; kt < 32; kt++) {
        int buf = kt & 1;
        if (kt < 31)
            asm volatile("cp.async.wait_group 1;" ::: "memory");
        else
            asm volatile("cp.async.wait_group 0;" ::: "memory");
        __syncthreads();

        const float (*A)[A_STRIDE] = As[buf];
        const float (*Bc)[B_STRIDE] = Bs[buf];
#pragma unroll
        for (int kk = 0; kk < 4; kk++) {
            int k0 = kk * 8 + (lane & 3);
            unsigned a[4][4];
#pragma unroll
            for (int mf = 0; mf < 4; mf++) {
                int r0 = wm * 64 + mf * 16 + (lane >> 2);
                a[mf][0] = __float_as_uint(A[r0][k0]);
                a[mf][1] = __float_as_uint(A[r0 + 8][k0]);
                a[mf][2] = __float_as_uint(A[r0][k0 + 4]);
                a[mf][3] = __float_as_uint(A[r0 + 8][k0 + 4]);
            }
            unsigned bf[8][2];
#pragma unroll
            for (int nf = 0; nf < 8; nf++) {
                int n0 = wn * 64 + nf * 8 + (lane >> 2);
                bf[nf][0] = __float_as_uint(Bc[k0][n0]);
                bf[nf][1] = __float_as_uint(Bc[k0 + 4][n0]);
            }
#pragma unroll
            for (int mf = 0; mf < 4; mf++)
#pragma unroll
                for (int nf = 0; nf < 8; nf++)
                    asm("mma.sync.aligned.m16n8k8.row.col.f32.tf32.tf32.f32 "
                        "{%0,%1,%2,%3}, {%4,%5,%6,%7}, {%8,%9}, {%0,%1,%2,%3};"
                        : "+f"(c[mf][nf][0]), "+f"(c[mf][nf][1]),
                          "+f"(c[mf][nf][2]), "+f"(c[mf][nf][3])
                        : "r"(a[mf][0]), "r"(a[mf][1]), "r"(a[mf][2]), "r"(a[mf][3]),
                          "r"(bf[nf][0]), "r"(bf[nf][1]));
        }
        __syncthreads();             // all warps done with buf before refill
        if (kt + 2 < 32) LOAD_TILE((kt + 2) * 32, buf);
    }

    // ---- fused epilogue: per-row LN affine + exact GELU + segmented atomic sums ----
    int bseg = (bm / LL) * SS;
    int rbase = bm + wm * 64 + (lane >> 2);
    float rrs[8], rmm[8];   // rstd, rstd*mu
    int   rsg[8];
#pragma unroll
    for (int i = 0; i < 8; i++) {
        int r = rbase + i * 8;
        float rs = g_rstd[r];
        rrs[i] = rs;
        rmm[i] = rs * g_mu[r];
        rsg[i] = g_seg[r];
    }
#pragma unroll
    for (int nf = 0; nf < 8; nf++) {
#pragma unroll
        for (int cs = 0; cs < 2; cs++) {
            int n = bn + wn * 64 + nf * 8 + (lane & 3) * 2 + cs;
            float csum = g_colsum[n];
            float bw   = g_bw[n];
            float acc = 0.f;
            int cur = -1;
#pragma unroll
            for (int i = 0; i < 8; i++) {
                int mf = i >> 1, sub = i & 1;
                int s = rsg[i];
                float cv = c[mf][nf][sub * 2 + cs];
                float val = fmaf(rrs[i], cv, fmaf(-rmm[i], csum, bw));
                val = 0.5f * val * (1.f + erff(val * 0.70710678118f));
                if (s >= 0) {
                    if (s != cur) {
                        if (cur >= 0) atomicAdd(&g_segsum[(bseg + cur) * NN + n], acc);
                        cur = s;
                        acc = 0.f;
                    }
                    acc += val;
                }
            }
            if (cur >= 0) atomicAdd(&g_segsum[(bseg + cur) * NN + n], acc);
        }
    }
#undef LOAD_TILE
}

// ===================== K5: per-batch tail (softmax, doc emb, final LN+GEMMs) =====================
__global__ void finalize_kernel(const float* __restrict__ as_s, const float* __restrict__ as_b,
                                const float* __restrict__ Wasp,
                                const float* __restrict__ se_s, const float* __restrict__ se_b,
                                const float* __restrict__ Wse,
                                float* __restrict__ out_result, float* __restrict__ out_asp) {
    int b = blockIdx.x;
    int t = threadIdx.x;          // 256
    __shared__ float docsum[NASP][256];
    __shared__ float wsum[NASP];
    __shared__ float red[512];    // [0..255]=sum tree, [256..511]=sumsq tree
    __shared__ float part[9][256];
    __shared__ float logits[9];
    __shared__ int   pis[SS];
    if (t < SS) pis[t] = g_pi[b * SS + t];
    if (t < NASP) wsum[t] = 0.f;
    for (int j = 0; j < NASP; j++) docsum[j][t] = 0.f;
    __syncthreads();

    for (int s = 0; s < SS; s++) {
        int end = pis[s];
        int start = (s == 0) ? 0 : (pis[s - 1] + 1);
        float inv_cnt = 1.0f / (float)(end - start);
        const float* seg = g_segsum + ((b * SS) + s) * NN;
        float aval = seg[t] * inv_cnt;
        float sval = seg[256 + t] * inv_cnt;
        // LN(a_sent) over 256
        red[t] = aval; red[256 + t] = aval * aval;
        __syncthreads();
        for (int o = 128; o > 0; o >>= 1) {
            if (t < o) { red[t] += red[t + o]; red[256 + t] += red[256 + t + o]; }
            __syncthreads();
        }
        float mu = red[0] * (1.0f / 256.f);
        float var = red[256] * (1.0f / 256.f) - mu * mu;
        float r = rsqrtf(var + 1e-5f);
        float ln = (aval - mu) * r * as_s[t] + as_b[t];
        for (int j = 0; j < 9; j++) part[j][t] = ln * Wasp[t * 9 + j];
        __syncthreads();
        for (int o = 128; o > 0; o >>= 1) {
            if (t < o) for (int j = 0; j < 9; j++) part[j][t] += part[j][t + o];
            __syncthreads();
        }
        if (t < 9) logits[t] = part[t][0];
        __syncthreads();
        float mx = -1e30f;
        for (int j = 0; j < 9; j++) mx = fmaxf(mx, logits[j]);
        float ex[9]; float den = 0.f;
        for (int j = 0; j < 9; j++) { ex[j] = expf(logits[j] - mx); den += ex[j]; }
        float inv = 1.f / den;
        if (t < 9) out_asp[(b * SS + s) * 9 + t] = ex[t] * inv;
        for (int j = 0; j < NASP; j++) docsum[j][t] += (ex[j] * inv) * sval;
        if (t == 0) for (int j = 0; j < NASP; j++) wsum[j] += ex[j] * inv;
        __syncthreads();
    }

    for (int j = 0; j < NASP; j++) {
        float emb = docsum[j][t] / wsum[j];
        red[t] = emb; red[256 + t] = emb * emb;
        __syncthreads();
        for (int o = 128; o > 0; o >>= 1) {
            if (t < o) { red[t] += red[t + o]; red[256 + t] += red[256 + t + o]; }
            __syncthreads();
        }
        float mu = red[0] * (1.0f / 256.f);
        float var = red[256] * (1.0f / 256.f) - mu * mu;
        float r = rsqrtf(var + 1e-5f);
        float ln = (emb - mu) * r * se_s[t] + se_b[t];
        for (int q = 0; q < NRAT; q++) part[q][t] = ln * Wse[t * NRAT + q];
        __syncthreads();
        for (int o = 128; o > 0; o >>= 1) {
            if (t < o) for (int q = 0; q < NRAT; q++) part[q][t] += part[q][t + o];
            __syncthreads();
        }
        if (t < NRAT) out_result[(b * NASP + j) * NRAT + t] = part[t][0];
        __syncthreads();
    }
}

// ===================== launch =====================
extern "C" void kernel_launch(void* const* d_in, const int* in_sizes, int n_in,
                              void* d_out, int out_size) {
    const float* X       = (const float*)d_in[0];
    const int*   p_index = (const int*)d_in[2];
    // n_sent may appear as a 1-element int input at index 3; params follow
    int base = (in_sizes[3] == 1) ? 4 : 3;
    const float* ln_a_s  = (const float*)d_in[base + 0];
    const float* ln_a_b  = (const float*)d_in[base + 1];
    const float* W_a     = (const float*)d_in[base + 2];
    const float* ln_s_s  = (const float*)d_in[base + 3];
    const float* ln_s_b  = (const float*)d_in[base + 4];
    const float* W_s     = (const float*)d_in[base + 5];
    const float* ln_asp_s= (const float*)d_in[base + 6];
    const float* ln_asp_b= (const float*)d_in[base + 7];
    const float* W_asp   = (const float*)d_in[base + 8];
    const float* ln_se_s = (const float*)d_in[base + 9];
    const float* ln_se_b = (const float*)d_in[base + 10];
    const float* W_se    = (const float*)d_in[base + 11];

    float* out        = (float*)d_out;
    float* out_result = out + OFF_RESULT;
    float* out_X      = out + OFF_X;
    float* out_asp    = out + OFF_ASP;

    static int smem_set = 0;
    if (!smem_set) {
        cudaFuncSetAttribute(gemm_kernel, cudaFuncAttributeMaxDynamicSharedMemorySize,
                             SMEM_BYTES);
        smem_set = 1;
    }

    prep_kernel<<<NN, 256>>>(W_a, W_s, ln_a_s, ln_a_b, ln_s_s, ln_s_b);
    seg_kernel<<<BB, 256>>>(p_index);
    zero_segsum_kernel<<<256, 256>>>();
    rowstats_copy_kernel<<<MM, 256>>>(X, out_X);
    float* Xt;
    cudaGetSymbolAddress((void**)&Xt, g_Xt);
    dim3 g3(NN / 256, MM / 128);        // (2, 256)
    gemm_kernel<<<g3, 256, SMEM_BYTES>>>(Xt);
    finalize_kernel<<<BB, 256>>>(ln_asp_s, ln_asp_b, W_asp, ln_se_s, ln_se_b, W_se,
                                 out_result, out_asp);
}

// round 14
// speedup vs baseline: 1.0005x; 1.0005x over previous
#include <cuda_runtime.h>
#include <math.h>
#include <stdint.h>

// Problem constants (fixed shapes)
#define BB   16
#define LL   2048
#define HH   1024
#define SS   32
#define PP   256
#define NN   512            // 2*P combined GEMM width (a | s)
#define MM   (BB*LL)        // 32768 rows
#define NASP 8
#define NRAT 5

// Output layout: (result[B,8,5], outputs[B,L,H], aspect_doc[B,32,9]) flattened
#define OFF_RESULT 0
#define OFF_X      640
#define OFF_ASP    (640 + BB*LL*HH)

// -------- device scratch (static; no runtime allocation allowed) --------
__device__ float g_Wc[HH * NN];            // folded, tf32-rounded weights (k-major)
__device__ float g_Xt[(size_t)MM * HH];    // tf32-rounded copy of X (A operand)
__device__ float g_colsum[NN];             // sum_h s_h*W[h,n]
__device__ float g_bw[NN];                 // sum_h b_h*W[h,n]
__device__ float g_mu[MM];
__device__ float g_rstd[MM];
__device__ int   g_seg[MM];                // segment id per row, -1 = excluded
__device__ int   g_pi[BB * SS];            // boundary positions
__device__ float g_segsum[BB * SS * NN];

// ===================== K0: fold LN scale/bias into weights =====================
__global__ void prep_kernel(const float* __restrict__ Wa, const float* __restrict__ Ws,
                            const float* __restrict__ sa, const float* __restrict__ ba,
                            const float* __restrict__ ss, const float* __restrict__ bs) {
    int n = blockIdx.x;           // 0..511
    int t = threadIdx.x;          // 256
    bool isA = (n < PP);
    const float* W  = isA ? Wa : Ws;
    const float* sv = isA ? sa : ss;
    const float* bv = isA ? ba : bs;
    int nc = isA ? n : (n - PP);
    float cs = 0.f, bw = 0.f;
    for (int k = t; k < HH; k += 256) {
        float w = W[k * PP + nc];
        float f = sv[k] * w;
        unsigned u;
        asm("cvt.rna.tf32.f32 %0, %1;" : "=r"(u) : "f"(f));
        g_Wc[k * NN + n] = __uint_as_float(u);
        cs += f;
        bw += bv[k] * w;
    }
    __shared__ float r1[256], r2[256];
    r1[t] = cs; r2[t] = bw;
    __syncthreads();
    for (int o = 128; o > 0; o >>= 1) {
        if (t < o) { r1[t] += r1[t + o]; r2[t] += r2[t + o]; }
        __syncthreads();
    }
    if (t == 0) { g_colsum[n] = r1[0]; g_bw[n] = r2[0]; }
}

// ===== K1: per-row mean/rstd + passthrough copy + tf32-rounded A operand =====
__global__ void rowstats_copy_kernel(const float* __restrict__ X, float* __restrict__ outX) {
    int row = blockIdx.x;
    int t = threadIdx.x;          // 256, one float4 each
    float4 v = ((const float4*)X)[(size_t)row * 256 + t];
    ((float4*)outX)[(size_t)row * 256 + t] = v;
    // tf32 round-to-nearest copy for the GEMM A operand
    unsigned u0, u1, u2, u3;
    asm("cvt.rna.tf32.f32 %0, %1;" : "=r"(u0) : "f"(v.x));
    asm("cvt.rna.tf32.f32 %0, %1;" : "=r"(u1) : "f"(v.y));
    asm("cvt.rna.tf32.f32 %0, %1;" : "=r"(u2) : "f"(v.z));
    asm("cvt.rna.tf32.f32 %0, %1;" : "=r"(u3) : "f"(v.w));
    float4 w = make_float4(__uint_as_float(u0), __uint_as_float(u1),
                           __uint_as_float(u2), __uint_as_float(u3));
    ((float4*)g_Xt)[(size_t)row * 256 + t] = w;

    float s = v.x + v.y + v.z + v.w;
    float q = v.x * v.x + v.y * v.y + v.z * v.z + v.w * v.w;
    for (int o = 16; o > 0; o >>= 1) {
        s += __shfl_down_sync(0xffffffffu, s, o);
        q += __shfl_down_sync(0xffffffffu, q, o);
    }
    __shared__ float wsm[8], wqm[8];
    if ((t & 31) == 0) { wsm[t >> 5] = s; wqm[t >> 5] = q; }
    __syncthreads();
    if (t == 0) {
        float S = 0.f, Q = 0.f;
        for (int i = 0; i < 8; i++) { S += wsm[i]; Q += wqm[i]; }
        float mu = S * (1.0f / HH);
        float var = Q * (1.0f / HH) - mu * mu;
        g_mu[row] = mu;
        g_rstd[row] = rsqrtf(var + 1e-5f);
    }
}

// ===================== K2: segment id per row + boundary positions =====================
__global__ void seg_kernel(const int* __restrict__ p) {
    int b = blockIdx.x;
    int t = threadIdx.x;          // 256 threads, 8 positions each
    const int* pb = p + b * LL;
    int base = t * 8;
    int cnt = 0;
#pragma unroll
    for (int i = 0; i < 8; i++) cnt += (pb[base + i] > 0);
    __shared__ int sc[256];
    sc[t] = cnt;
    __syncthreads();
    for (int o = 1; o < 256; o <<= 1) {
        int v = (t >= o) ? sc[t - o] : 0;
        __syncthreads();
        sc[t] += v;
        __syncthreads();
    }
    int k = (t > 0) ? sc[t - 1] : 0;  // exclusive prefix: boundaries before chunk
#pragma unroll
    for (int i = 0; i < 8; i++) {
        int pos = base + i;
        if (pb[pos] > 0) {
            if (k < SS) g_pi[b * SS + k] = pos;
            g_seg[b * LL + pos] = -1;     // boundary row excluded
            k++;
        } else {
            g_seg[b * LL + pos] = (k < SS) ? k : -1;
        }
    }
}

// ===================== K2b: zero the segment-sum accumulator (graph-replay safe) ==========
__global__ void zero_segsum_kernel() {
    int i = blockIdx.x * 256 + threadIdx.x;   // 65536 float4 = 262144 floats
    ((float4*)g_segsum)[i] = make_float4(0.f, 0.f, 0.f, 0.f);
}

// ===================== K3: tf32 mma.sync GEMM 128x256 tile, cp.async 2-stage =====
// + fused LN/GELU/segmented-sum epilogue
#define A_STRIDE 36
#define B_STRIDE 260
#define SMEM_FLOATS (2 * (128 * A_STRIDE) + 2 * (32 * B_STRIDE))
#define SMEM_BYTES  (SMEM_FLOATS * 4)      // 103424 bytes

__global__ void __launch_bounds__(256, 1) gemm_kernel(const float* __restrict__ Xt) {
    extern __shared__ float smem[];
    float (*As)[128][A_STRIDE] = (float (*)[128][A_STRIDE])smem;
    float (*Bs)[32][B_STRIDE]  = (float (*)[32][B_STRIDE])(smem + 2 * 128 * A_STRIDE);

    int tid = threadIdx.x;
    int lane = tid & 31, wid = tid >> 5;
    int wm = wid & 1, wn = wid >> 1;       // 2 warps (M, 64 rows) x 4 warps (N, 64 cols)
    int bm = blockIdx.y * 128;
    int bn = blockIdx.x * 256;

    // per-thread load coordinates (fixed across tiles)
    int a_row = tid >> 3;            // 0..31 (stepped by 32 over j)
    int a_col = (tid & 7) * 4;       // 0,4,...,28
    int b_kr  = tid >> 6;            // 0..3 (stepped by 4 over j)
    int b_nc  = (tid & 63) * 4;      // 0..252

    const float* a_base = Xt + (size_t)(bm + a_row) * HH + a_col;
    const float* b_base = g_Wc + (size_t)b_kr * NN + bn + b_nc;

    float c[4][8][4];
#pragma unroll
    for (int i = 0; i < 4; i++)
#pragma unroll
        for (int j = 0; j < 8; j++)
#pragma unroll
            for (int r = 0; r < 4; r++) c[i][j][r] = 0.f;

#define LOAD_TILE(KT, BUF)                                                          \
    do {                                                                            \
        _Pragma("unroll")                                                           \
        for (int j = 0; j < 4; j++) {   /* A: 128x32 = 1024 float4 */               \
            unsigned dst = (unsigned)__cvta_generic_to_shared(                      \
                &As[BUF][j * 32 + a_row][a_col]);                                   \
            const float* src = a_base + (size_t)(j * 32) * HH + (KT);               \
            asm volatile("cp.async.cg.shared.global [%0], [%1], 16;"                \
                         :: "r"(dst), "l"(src) : "memory");                         \
        }                                                                           \
        _Pragma("unroll")                                                           \
        for (int j = 0; j < 8; j++) {   /* B: 32x256 = 2048 float4 */               \
            unsigned dst = (unsigned)__cvta_generic_to_shared(                      \
                &Bs[BUF][j * 4 + b_kr][b_nc]);                                      \
            const float* src = b_base + (size_t)((KT) + j * 4) * NN;                \
            asm volatile("cp.async.cg.shared.global [%0], [%1], 16;"                \
                         :: "r"(dst), "l"(src) : "memory");                         \
        }                                                                           \
        asm volatile("cp.async.commit_group;" ::: "memory");                        \
    } while (0)

    LOAD_TILE(0, 0);
    LOAD_TILE(32, 1);

    for (int kt = 0; kt < 32; kt++) {
        int buf = kt & 1;
        if (kt < 31)
            asm volatile("cp.async.wait_group 1;" ::: "memory");
        else
            asm volatile("cp.async.wait_group 0;" ::: "memory");
        __syncthreads();

        const float (*A)[A_STRIDE] = As[buf];
        const float (*Bc)[B_STRIDE] = Bs[buf];
#pragma unroll
        for (int kk = 0; kk < 4; kk++) {
            int k0 = kk * 8 + (lane & 3);
            unsigned a[4][4];
#pragma unroll
            for (int mf = 0; mf < 4; mf++) {
                int r0 = wm * 64 + mf * 16 + (lane >> 2);
                a[mf][0] = __float_as_uint(A[r0][k0]);
                a[mf][1] = __float_as_uint(A[r0 + 8][k0]);
                a[mf][2] = __float_as_uint(A[r0][k0 + 4]);
                a[mf][3] = __float_as_uint(A[r0 + 8][k0 + 4]);
            }
            unsigned bf[8][2];
#pragma unroll
            for (int nf = 0; nf < 8; nf++) {
                int n0 = wn * 64 + nf * 8 + (lane >> 2);
                bf[nf][0] = __float_as_uint(Bc[k0][n0]);
                bf[nf][1] = __float_as_uint(Bc[k0 + 4][n0]);
            }
#pragma unroll
            for (int mf = 0; mf < 4; mf++)
#pragma unroll
                for (int nf = 0; nf < 8; nf++)
                    asm("mma.sync.aligned.m16n8k8.row.col.f32.tf32.tf32.f32 "
                        "{%0,%1,%2,%3}, {%4,%5,%6,%7}, {%8,%9}, {%0,%1,%2,%3};"
                        : "+f"(c[mf][nf][0]), "+f"(c[mf][nf][1]),
                          "+f"(c[mf][nf][2]), "+f"(c[mf][nf][3])
                        : "r"(a[mf][0]), "r"(a[mf][1]), "r"(a[mf][2]), "r"(a[mf][3]),
                          "r"(bf[nf][0]), "r"(bf[nf][1]));
        }
        __syncthreads();             // all warps done with buf before refill
        if (kt + 2 < 32) LOAD_TILE((kt + 2) * 32, buf);
    }

    // ---- fused epilogue: per-row LN affine + exact GELU + segmented atomic sums ----
    int bseg = (bm / LL) * SS;
    int rbase = bm + wm * 64 + (lane >> 2);
    float rrs[8], rmm[8];   // rstd, rstd*mu
    int   rsg[8];
#pragma unroll
    for (int i = 0; i < 8; i++) {
        int r = rbase + i * 8;
        float rs = g_rstd[r];
        rrs[i] = rs;
        rmm[i] = rs * g_mu[r];
        rsg[i] = g_seg[r];
    }
#pragma unroll
    for (int nf = 0; nf < 8; nf++) {
#pragma unroll
        for (int cs = 0; cs < 2; cs++) {
            int n = bn + wn * 64 + nf * 8 + (lane & 3) * 2 + cs;
            float csum = g_colsum[n];
            float bw   = g_bw[n];
            float acc = 0.f;
            int cur = -1;
#pragma unroll
            for (int i = 0; i < 8; i++) {
                int mf = i >> 1, sub = i & 1;
                int s = rsg[i];
                float cv = c[mf][nf][sub * 2 + cs];
                float val = fmaf(rrs[i], cv, fmaf(-rmm[i], csum, bw));
                val = 0.5f * val * (1.f + erff(val * 0.70710678118f));
                if (s >= 0) {
                    if (s != cur) {
                        if (cur >= 0) atomicAdd(&g_segsum[(bseg + cur) * NN + n], acc);
                        cur = s;
                        acc = 0.f;
                    }
                    acc += val;
                }
            }
            if (cur >= 0) atomicAdd(&g_segsum[(bseg + cur) * NN + n], acc);
        }
    }
#undef LOAD_TILE
}

// ===================== K5: per-batch tail (softmax, doc emb, final LN+GEMMs) =====================
__global__ void finalize_kernel(const float* __restrict__ as_s, const float* __restrict__ as_b,
                                const float* __restrict__ Wasp,
                                const float* __restrict__ se_s, const float* __restrict__ se_b,
                                const float* __restrict__ Wse,
                                float* __restrict__ out_result, float* __restrict__ out_asp) {
    int b = blockIdx.x;
    int t = threadIdx.x;          // 256
    __shared__ float docsum[NASP][256];
    __shared__ float wsum[NASP];
    __shared__ float red[512];    // [0..255]=sum tree, [256..511]=sumsq tree
    __shared__ float part[9][256];
    __shared__ float logits[9];
    __shared__ int   pis[SS];
    if (t < SS) pis[t] = g_pi[b * SS + t];
    if (t < NASP) wsum[t] = 0.f;
    for (int j = 0; j < NASP; j++) docsum[j][t] = 0.f;
    __syncthreads();

    for (int s = 0; s < SS; s++) {
        int end = pis[s];
        int start = (s == 0) ? 0 : (pis[s - 1] + 1);
        float inv_cnt = 1.0f / (float)(end - start);
        const float* seg = g_segsum + ((b * SS) + s) * NN;
        float aval = seg[t] * inv_cnt;
        float sval = seg[256 + t] * inv_cnt;
        // LN(a_sent) over 256
        red[t] = aval; red[256 + t] = aval * aval;
        __syncthreads();
        for (int o = 128; o > 0; o >>= 1) {
            if (t < o) { red[t] += red[t + o]; red[256 + t] += red[256 + t + o]; }
            __syncthreads();
        }
        float mu = red[0] * (1.0f / 256.f);
        float var = red[256] * (1.0f / 256.f) - mu * mu;
        float r = rsqrtf(var + 1e-5f);
        float ln = (aval - mu) * r * as_s[t] + as_b[t];
        for (int j = 0; j < 9; j++) part[j][t] = ln * Wasp[t * 9 + j];
        __syncthreads();
        for (int o = 128; o > 0; o >>= 1) {
            if (t < o) for (int j = 0; j < 9; j++) part[j][t] += part[j][t + o];
            __syncthreads();
        }
        if (t < 9) logits[t] = part[t][0];
        __syncthreads();
        float mx = -1e30f;
        for (int j = 0; j < 9; j++) mx = fmaxf(mx, logits[j]);
        float ex[9]; float den = 0.f;
        for (int j = 0; j < 9; j++) { ex[j] = expf(logits[j] - mx); den += ex[j]; }
        float inv = 1.f / den;
        if (t < 9) out_asp[(b * SS + s) * 9 + t] = ex[t] * inv;
        for (int j = 0; j < NASP; j++) docsum[j][t] += (ex[j] * inv) * sval;
        if (t == 0) for (int j = 0; j < NASP; j++) wsum[j] += ex[j] * inv;
        __syncthreads();
    }

    for (int j = 0; j < NASP; j++) {
        float emb = docsum[j][t] / wsum[j];
        red[t] = emb; red[256 + t] = emb * emb;
        __syncthreads();
        for (int o = 128; o > 0; o >>= 1) {
            if (t < o) { red[t] += red[t + o]; red[256 + t] += red[256 + t + o]; }
            __syncthreads();
        }
        float mu = red[0] * (1.0f / 256.f);
        float var = red[256] * (1.0f / 256.f) - mu * mu;
        float r = rsqrtf(var + 1e-5f);
        float ln = (emb - mu) * r * se_s[t] + se_b[t];
        for (int q = 0; q < NRAT; q++) part[q][t] = ln * Wse[t * NRAT + q];
        __syncthreads();
        for (int o = 128; o > 0; o >>= 1) {
            if (t < o) for (int q = 0; q < NRAT; q++) part[q][t] += part[q][t + o];
            __syncthreads();
        }
        if (t < NRAT) out_result[(b * NASP + j) * NRAT + t] = part[t][0];
        __syncthreads();
    }
}

// ===================== launch =====================
extern "C" void kernel_launch(void* const* d_in, const int* in_sizes, int n_in,
                              void* d_out, int out_size) {
    const float* X       = (const float*)d_in[0];
    const int*   p_index = (const int*)d_in[2];
    // n_sent may appear as a 1-element int input at index 3; params follow
    int base = (in_sizes[3] == 1) ? 4 : 3;
    const float* ln_a_s  = (const float*)d_in[base + 0];
    const float* ln_a_b  = (const float*)d_in[base + 1];
    const float* W_a     = (const float*)d_in[base + 2];
    const float* ln_s_s  = (const float*)d_in[base + 3];
    const float* ln_s_b  = (const float*)d_in[base + 4];
    const float* W_s     = (const float*)d_in[base + 5];
    const float* ln_asp_s= (const float*)d_in[base + 6];
    const float* ln_asp_b= (const float*)d_in[base + 7];
    const float* W_asp   = (const float*)d_in[base + 8];
    const float* ln_se_s = (const float*)d_in[base + 9];
    const float* ln_se_b = (const float*)d_in[base + 10];
    const float* W_se    = (const float*)d_in[base + 11];

    float* out        = (float*)d_out;
    float* out_result = out + OFF_RESULT;
    float* out_X      = out + OFF_X;
    float* out_asp    = out + OFF_ASP;

    static int smem_set = 0;
    if (!smem_set) {
        cudaFuncSetAttribute(gemm_kernel, cudaFuncAttributeMaxDynamicSharedMemorySize,
                             SMEM_BYTES);
        smem_set = 1;
    }

    prep_kernel<<<NN, 256>>>(W_a, W_s, ln_a_s, ln_a_b, ln_s_s, ln_s_b);
    seg_kernel<<<BB, 256>>>(p_index);
    zero_segsum_kernel<<<256, 256>>>();
    rowstats_copy_kernel<<<MM, 256>>>(X, out_X);
    float* Xt;
    cudaGetSymbolAddress((void**)&Xt, g_Xt);
    dim3 g3(NN / 256, MM / 128);        // (2, 256)
    gemm_kernel<<<g3, 256, SMEM_BYTES>>>(Xt);
    finalize_kernel<<<BB, 256>>>(ln_asp_s, ln_asp_b, W_asp, ln_se_s, ln_se_b, W_se,
                                 out_result, out_asp);
}

// round 15
// speedup vs baseline: 1.0027x; 1.0022x over previous
#include <cuda_runtime.h>
#include <math.h>
#include <stdint.h>

// Problem constants (fixed shapes)
#define BB   16
#define LL   2048
#define HH   1024
#define SS   32
#define PP   256
#define NN   512            // 2*P combined GEMM width (a | s)
#define MM   (BB*LL)        // 32768 rows
#define NASP 8
#define NRAT 5

// Output layout: (result[B,8,5], outputs[B,L,H], aspect_doc[B,32,9]) flattened
#define OFF_RESULT 0
#define OFF_X      640
#define OFF_ASP    (640 + BB*LL*HH)

// -------- device scratch (static; no runtime allocation allowed) --------
__device__ float g_Wc[HH * NN];            // folded, tf32-rounded weights (k-major)
__device__ float g_Xt[(size_t)MM * HH];    // tf32-rounded copy of X (A operand)
__device__ float g_colsum[NN];             // sum_h s_h*W[h,n]
__device__ float g_bw[NN];                 // sum_h b_h*W[h,n]
__device__ float g_mu[MM];
__device__ float g_rstd[MM];
__device__ int   g_seg[MM];                // segment id per row, -1 = excluded
__device__ int   g_pi[BB * SS];            // boundary positions
__device__ float g_segsum[BB * SS * NN];

// ===================== K0: fold LN scale/bias into weights =====================
__global__ void prep_kernel(const float* __restrict__ Wa, const float* __restrict__ Ws,
                            const float* __restrict__ sa, const float* __restrict__ ba,
                            const float* __restrict__ ss, const float* __restrict__ bs) {
    int n = blockIdx.x;           // 0..511
    int t = threadIdx.x;          // 256
    bool isA = (n < PP);
    const float* W  = isA ? Wa : Ws;
    const float* sv = isA ? sa : ss;
    const float* bv = isA ? ba : bs;
    int nc = isA ? n : (n - PP);
    float cs = 0.f, bw = 0.f;
    for (int k = t; k < HH; k += 256) {
        float w = W[k * PP + nc];
        float f = sv[k] * w;
        unsigned u;
        asm("cvt.rna.tf32.f32 %0, %1;" : "=r"(u) : "f"(f));
        g_Wc[k * NN + n] = __uint_as_float(u);
        cs += f;
        bw += bv[k] * w;
    }
    __shared__ float r1[256], r2[256];
    r1[t] = cs; r2[t] = bw;
    __syncthreads();
    for (int o = 128; o > 0; o >>= 1) {
        if (t < o) { r1[t] += r1[t + o]; r2[t] += r2[t + o]; }
        __syncthreads();
    }
    if (t == 0) { g_colsum[n] = r1[0]; g_bw[n] = r2[0]; }
}

// ===== K1: per-row mean/rstd + passthrough copy + tf32-rounded A operand =====
__global__ void rowstats_copy_kernel(const float* __restrict__ X, float* __restrict__ outX) {
    int row = blockIdx.x;
    int t = threadIdx.x;          // 256, one float4 each
    float4 v = ((const float4*)X)[(size_t)row * 256 + t];
    ((float4*)outX)[(size_t)row * 256 + t] = v;
    // tf32 round-to-nearest copy for the GEMM A operand
    unsigned u0, u1, u2, u3;
    asm("cvt.rna.tf32.f32 %0, %1;" : "=r"(u0) : "f"(v.x));
    asm("cvt.rna.tf32.f32 %0, %1;" : "=r"(u1) : "f"(v.y));
    asm("cvt.rna.tf32.f32 %0, %1;" : "=r"(u2) : "f"(v.z));
    asm("cvt.rna.tf32.f32 %0, %1;" : "=r"(u3) : "f"(v.w));
    float4 w = make_float4(__uint_as_float(u0), __uint_as_float(u1),
                           __uint_as_float(u2), __uint_as_float(u3));
    ((float4*)g_Xt)[(size_t)row * 256 + t] = w;

    float s = v.x + v.y + v.z + v.w;
    float q = v.x * v.x + v.y * v.y + v.z * v.z + v.w * v.w;
    for (int o = 16; o > 0; o >>= 1) {
        s += __shfl_down_sync(0xffffffffu, s, o);
        q += __shfl_down_sync(0xffffffffu, q, o);
    }
    __shared__ float wsm[8], wqm[8];
    if ((t & 31) == 0) { wsm[t >> 5] = s; wqm[t >> 5] = q; }
    __syncthreads();
    if (t == 0) {
        float S = 0.f, Q = 0.f;
        for (int i = 0; i < 8; i++) { S += wsm[i]; Q += wqm[i]; }
        float mu = S * (1.0f / HH);
        float var = Q * (1.0f / HH) - mu * mu;
        g_mu[row] = mu;
        g_rstd[row] = rsqrtf(var + 1e-5f);
    }
}

// ===================== K2: segment id per row + boundary positions =====================
__global__ void seg_kernel(const int* __restrict__ p) {
    int b = blockIdx.x;
    int t = threadIdx.x;          // 256 threads, 8 positions each
    const int* pb = p + b * LL;
    int base = t * 8;
    int cnt = 0;
#pragma unroll
    for (int i = 0; i < 8; i++) cnt += (pb[base + i] > 0);
    __shared__ int sc[256];
    sc[t] = cnt;
    __syncthreads();
    for (int o = 1; o < 256; o <<= 1) {
        int v = (t >= o) ? sc[t - o] : 0;
        __syncthreads();
        sc[t] += v;
        __syncthreads();
    }
    int k = (t > 0) ? sc[t - 1] : 0;  // exclusive prefix: boundaries before chunk
#pragma unroll
    for (int i = 0; i < 8; i++) {
        int pos = base + i;
        if (pb[pos] > 0) {
            if (k < SS) g_pi[b * SS + k] = pos;
            g_seg[b * LL + pos] = -1;     // boundary row excluded
            k++;
        } else {
            g_seg[b * LL + pos] = (k < SS) ? k : -1;
        }
    }
}

// ===================== K2b: zero the segment-sum accumulator (graph-replay safe) ==========
__global__ void zero_segsum_kernel() {
    int i = blockIdx.x * 256 + threadIdx.x;   // 65536 float4 = 262144 floats
    ((float4*)g_segsum)[i] = make_float4(0.f, 0.f, 0.f, 0.f);
}

// ===================== K3: tf32 mma.sync GEMM 128x256 tile, cp.async 2-stage =====
// + fused LN/GELU/segmented-sum epilogue
#define A_STRIDE 36
#define B_STRIDE 260
#define SMEM_FLOATS (2 * (128 * A_STRIDE) + 2 * (32 * B_STRIDE))
#define SMEM_BYTES  (SMEM_FLOATS * 4)      // 103424 bytes

__global__ void __launch_bounds__(256, 1) gemm_kernel(const float* __restrict__ Xt) {
    extern __shared__ float smem[];
    float (*As)[128][A_STRIDE] = (float (*)[128][A_STRIDE])smem;
    float (*Bs)[32][B_STRIDE]  = (float (*)[32][B_STRIDE])(smem + 2 * 128 * A_STRIDE);

    int tid = threadIdx.x;
    int lane = tid & 31, wid = tid >> 5;
    int wm = wid & 1, wn = wid >> 1;       // 2 warps (M, 64 rows) x 4 warps (N, 64 cols)
    int bm = blockIdx.y * 128;
    int bn = blockIdx.x * 256;

    // per-thread load coordinates (fixed across tiles)
    int a_row = tid >> 3;            // 0..31 (stepped by 32 over j)
    int a_col = (tid & 7) * 4;       // 0,4,...,28
    int b_kr  = tid >> 6;            // 0..3 (stepped by 4 over j)
    int b_nc  = (tid & 63) * 4;      // 0..252

    const float* a_base = Xt + (size_t)(bm + a_row) * HH + a_col;
    const float* b_base = g_Wc + (size_t)b_kr * NN + bn + b_nc;

    float c[4][8][4];
#pragma unroll
    for (int i = 0; i < 4; i++)
#pragma unroll
        for (int j = 0; j < 8; j++)
#pragma unroll
            for (int r = 0; r < 4; r++) c[i][j][r] = 0.f;

#define LOAD_TILE(KT, BUF)                                                          \
    do {                                                                            \
        _Pragma("unroll")                                                           \
        for (int j = 0; j < 4; j++) {   /* A: 128x32 = 1024 float4 */               \
            unsigned dst = (unsigned)__cvta_generic_to_shared(                      \
                &As[BUF][j * 32 + a_row][a_col]);                                   \
            const float* src = a_base + (size_t)(j * 32) * HH + (KT);               \
            asm volatile("cp.async.cg.shared.global [%0], [%1], 16;"                \
                         :: "r"(dst), "l"(src) : "memory");                         \
        }                                                                           \
        _Pragma("unroll")                                                           \
        for (int j = 0; j < 8; j++) {   /* B: 32x256 = 2048 float4 */               \
            unsigned dst = (unsigned)__cvta_generic_to_shared(                      \
                &Bs[BUF][j * 4 + b_kr][b_nc]);                                      \
            const float* src = b_base + (size_t)((KT) + j * 4) * NN;                \
            asm volatile("cp.async.cg.shared.global [%0], [%1], 16;"                \
                         :: "r"(dst), "l"(src) : "memory");                         \
        }                                                                           \
        asm volatile("cp.async.commit_group;" ::: "memory");                        \
    } while (0)

    LOAD_TILE(0, 0);
    LOAD_TILE(32, 1);

    for (int kt = 0; kt < 32; kt++) {
        int buf = kt & 1;
        if (kt < 31)
            asm volatile("cp.async.wait_group 1;" ::: "memory");
        else
            asm volatile("cp.async.wait_group 0;" ::: "memory");
        __syncthreads();

        const float (*A)[A_STRIDE] = As[buf];
        const float (*Bc)[B_STRIDE] = Bs[buf];
#pragma unroll
        for (int kk = 0; kk < 4; kk++) {
            int k0 = kk * 8 + (lane & 3);
            unsigned a[4][4];
#pragma unroll
            for (int mf = 0; mf < 4; mf++) {
                int r0 = wm * 64 + mf * 16 + (lane >> 2);
                a[mf][0] = __float_as_uint(A[r0][k0]);
                a[mf][1] = __float_as_uint(A[r0 + 8][k0]);
                a[mf][2] = __float_as_uint(A[r0][k0 + 4]);
                a[mf][3] = __float_as_uint(A[r0 + 8][k0 + 4]);
            }
            unsigned bf[8][2];
#pragma unroll
            for (int nf = 0; nf < 8; nf++) {
                int n0 = wn * 64 + nf * 8 + (lane >> 2);
                bf[nf][0] = __float_as_uint(Bc[k0][n0]);
                bf[nf][1] = __float_as_uint(Bc[k0 + 4][n0]);
            }
#pragma unroll
            for (int mf = 0; mf < 4; mf++)
#pragma unroll
                for (int nf = 0; nf < 8; nf++)
                    asm("mma.sync.aligned.m16n8k8.row.col.f32.tf32.tf32.f32 "
                        "{%0,%1,%2,%3}, {%4,%5,%6,%7}, {%8,%9}, {%0,%1,%2,%3};"
                        : "+f"(c[mf][nf][0]), "+f"(c[mf][nf][1]),
                          "+f"(c[mf][nf][2]), "+f"(c[mf][nf][3])
                        : "r"(a[mf][0]), "r"(a[mf][1]), "r"(a[mf][2]), "r"(a[mf][3]),
                          "r"(bf[nf][0]), "r"(bf[nf][1]));
        }
        __syncthreads();             // all warps done with buf before refill
        if (kt + 2 < 32) LOAD_TILE((kt + 2) * 32, buf);
    }

    // ---- fused epilogue: per-row LN affine + exact GELU + segmented atomic sums ----
    int bseg = (bm / LL) * SS;
    int rbase = bm + wm * 64 + (lane >> 2);
    float rrs[8], rmm[8];   // rstd, rstd*mu
    int   rsg[8];
#pragma unroll
    for (int i = 0; i < 8; i++) {
        int r = rbase + i * 8;
        float rs = g_rstd[r];
        rrs[i] = rs;
        rmm[i] = rs * g_mu[r];
        rsg[i] = g_seg[r];
    }
#pragma unroll
    for (int nf = 0; nf < 8; nf++) {
#pragma unroll
        for (int cs = 0; cs < 2; cs++) {
            int n = bn + wn * 64 + nf * 8 + (lane & 3) * 2 + cs;
            float csum = g_colsum[n];
            float bw   = g_bw[n];
            float acc = 0.f;
            int cur = -1;
#pragma unroll
            for (int i = 0; i < 8; i++) {
                int mf = i >> 1, sub = i & 1;
                int s = rsg[i];
                float cv = c[mf][nf][sub * 2 + cs];
                float val = fmaf(rrs[i], cv, fmaf(-rmm[i], csum, bw));
                val = 0.5f * val * (1.f + erff(val * 0.70710678118f));
                if (s >= 0) {
                    if (s != cur) {
                        if (cur >= 0) atomicAdd(&g_segsum[(bseg + cur) * NN + n], acc);
                        cur = s;
                        acc = 0.f;
                    }
                    acc += val;
                }
            }
            if (cur >= 0) atomicAdd(&g_segsum[(bseg + cur) * NN + n], acc);
        }
    }
#undef LOAD_TILE
}

// ===================== K5: per-batch tail (softmax, doc emb, final LN+GEMMs) =====================
__global__ void finalize_kernel(const float* __restrict__ as_s, const float* __restrict__ as_b,
                                const float* __restrict__ Wasp,
                                const float* __restrict__ se_s, const float* __restrict__ se_b,
                                const float* __restrict__ Wse,
                                float* __restrict__ out_result, float* __restrict__ out_asp) {
    int b = blockIdx.x;
    int t = threadIdx.x;          // 256
    __shared__ float docsum[NASP][256];
    __shared__ float wsum[NASP];
    __shared__ float red[512];    // [0..255]=sum tree, [256..511]=sumsq tree
    __shared__ float part[9][256];
    __shared__ float logits[9];
    __shared__ int   pis[SS];
    if (t < SS) pis[t] = g_pi[b * SS + t];
    if (t < NASP) wsum[t] = 0.f;
    for (int j = 0; j < NASP; j++) docsum[j][t] = 0.f;
    __syncthreads();

    for (int s = 0; s < SS; s++) {
        int end = pis[s];
        int start = (s == 0) ? 0 : (pis[s - 1] + 1);
        float inv_cnt = 1.0f / (float)(end - start);
        const float* seg = g_segsum + ((b * SS) + s) * NN;
        float aval = seg[t] * inv_cnt;
        float sval = seg[256 + t] * inv_cnt;
        // LN(a_sent) over 256
        red[t] = aval; red[256 + t] = aval * aval;
        __syncthreads();
        for (int o = 128; o > 0; o >>= 1) {
            if (t < o) { red[t] += red[t + o]; red[256 + t] += red[256 + t + o]; }
            __syncthreads();
        }
        float mu = red[0] * (1.0f / 256.f);
        float var = red[256] * (1.0f / 256.f) - mu * mu;
        float r = rsqrtf(var + 1e-5f);
        float ln = (aval - mu) * r * as_s[t] + as_b[t];
        for (int j = 0; j < 9; j++) part[j][t] = ln * Wasp[t * 9 + j];
        __syncthreads();
        for (int o = 128; o > 0; o >>= 1) {
            if (t < o) for (int j = 0; j < 9; j++) part[j][t] += part[j][t + o];
            __syncthreads();
        }
        if (t < 9) logits[t] = part[t][0];
        __syncthreads();
        float mx = -1e30f;
        for (int j = 0; j < 9; j++) mx = fmaxf(mx, logits[j]);
        float ex[9]; float den = 0.f;
        for (int j = 0; j < 9; j++) { ex[j] = expf(logits[j] - mx); den += ex[j]; }
        float inv = 1.f / den;
        if (t < 9) out_asp[(b * SS + s) * 9 + t] = ex[t] * inv;
        for (int j = 0; j < NASP; j++) docsum[j][t] += (ex[j] * inv) * sval;
        if (t == 0) for (int j = 0; j < NASP; j++) wsum[j] += ex[j] * inv;
        __syncthreads();
    }

    for (int j = 0; j < NASP; j++) {
        float emb = docsum[j][t] / wsum[j];
        red[t] = emb; red[256 + t] = emb * emb;
        __syncthreads();
        for (int o = 128; o > 0; o >>= 1) {
            if (t < o) { red[t] += red[t + o]; red[256 + t] += red[256 + t + o]; }
            __syncthreads();
        }
        float mu = red[0] * (1.0f / 256.f);
        float var = red[256] * (1.0f / 256.f) - mu * mu;
        float r = rsqrtf(var + 1e-5f);
        float ln = (emb - mu) * r * se_s[t] + se_b[t];
        for (int q = 0; q < NRAT; q++) part[q][t] = ln * Wse[t * NRAT + q];
        __syncthreads();
        for (int o = 128; o > 0; o >>= 1) {
            if (t < o) for (int q = 0; q < NRAT; q++) part[q][t] += part[q][t + o];
            __syncthreads();
        }
        if (t < NRAT) out_result[(b * NASP + j) * NRAT + t] = part[t][0];
        __syncthreads();
    }
}

// ===================== launch =====================
extern "C" void kernel_launch(void* const* d_in, const int* in_sizes, int n_in,
                              void* d_out, int out_size) {
    const float* X       = (const float*)d_in[0];
    const int*   p_index = (const int*)d_in[2];
    // n_sent may appear as a 1-element int input at index 3; params follow
    int base = (in_sizes[3] == 1) ? 4 : 3;
    const float* ln_a_s  = (const float*)d_in[base + 0];
    const float* ln_a_b  = (const float*)d_in[base + 1];
    const float* W_a     = (const float*)d_in[base + 2];
    const float* ln_s_s  = (const float*)d_in[base + 3];
    const float* ln_s_b  = (const float*)d_in[base + 4];
    const float* W_s     = (const float*)d_in[base + 5];
    const float* ln_asp_s= (const float*)d_in[base + 6];
    const float* ln_asp_b= (const float*)d_in[base + 7];
    const float* W_asp   = (const float*)d_in[base + 8];
    const float* ln_se_s = (const float*)d_in[base + 9];
    const float* ln_se_b = (const float*)d_in[base + 10];
    const float* W_se    = (const float*)d_in[base + 11];

    float* out        = (float*)d_out;
    float* out_result = out + OFF_RESULT;
    float* out_X      = out + OFF_X;
    float* out_asp    = out + OFF_ASP;

    static int smem_set = 0;
    if (!smem_set) {
        cudaFuncSetAttribute(gemm_kernel, cudaFuncAttributeMaxDynamicSharedMemorySize,
                             SMEM_BYTES);
        smem_set = 1;
    }

    prep_kernel<<<NN, 256>>>(W_a, W_s, ln_a_s, ln_a_b, ln_s_s, ln_s_b);
    seg_kernel<<<BB, 256>>>(p_index);
    zero_segsum_kernel<<<256, 256>>>();
    rowstats_copy_kernel<<<MM, 256>>>(X, out_X);
    float* Xt;
    cudaGetSymbolAddress((void**)&Xt, g_Xt);
    dim3 g3(NN / 256, MM / 128);        // (2, 256)
    gemm_kernel<<<g3, 256, SMEM_BYTES>>>(Xt);
    finalize_kernel<<<BB, 256>>>(ln_asp_s, ln_asp_b, W_asp, ln_se_s, ln_se_b, W_se,
                                 out_result, out_asp);
}

// round 16
// speedup vs baseline: 1.1834x; 1.1802x over previous
#include <cuda_runtime.h>
#include <math.h>
#include <stdint.h>

// Problem constants (fixed shapes)
#define BB   16
#define LL   2048
#define HH   1024
#define SS   32
#define PP   256
#define NN   512            // 2*P combined GEMM width (a | s)
#define MM   (BB*LL)        // 32768 rows
#define NASP 8
#define NRAT 5

// Output layout: (result[B,8,5], outputs[B,L,H], aspect_doc[B,32,9]) flattened
#define OFF_RESULT 0
#define OFF_X      640
#define OFF_ASP    (640 + BB*LL*HH)

// -------- device scratch (static; no runtime allocation allowed) --------
__device__ float g_Wc[HH * NN];            // folded, tf32-rounded weights (k-major)
__device__ float g_colsum[NN];             // sum_h s_h*W[h,n]
__device__ float g_bw[NN];                 // sum_h b_h*W[h,n]
__device__ float g_mu[MM];
__device__ float g_rstd[MM];
__device__ int   g_seg[MM];                // segment id per row, -1 = excluded
__device__ int   g_pi[BB * SS];            // boundary positions
__device__ float g_segsum[BB * SS * NN];

// ===================== K0: fold LN scale/bias into weights =====================
__global__ void prep_kernel(const float* __restrict__ Wa, const float* __restrict__ Ws,
                            const float* __restrict__ sa, const float* __restrict__ ba,
                            const float* __restrict__ ss, const float* __restrict__ bs) {
    int n = blockIdx.x;           // 0..511
    int t = threadIdx.x;          // 256
    bool isA = (n < PP);
    const float* W  = isA ? Wa : Ws;
    const float* sv = isA ? sa : ss;
    const float* bv = isA ? ba : bs;
    int nc = isA ? n : (n - PP);
    float cs = 0.f, bw = 0.f;
    for (int k = t; k < HH; k += 256) {
        float w = W[k * PP + nc];
        float f = sv[k] * w;
        unsigned u;
        asm("cvt.rna.tf32.f32 %0, %1;" : "=r"(u) : "f"(f));
        g_Wc[k * NN + n] = __uint_as_float(u);
        cs += f;
        bw += bv[k] * w;
    }
    __shared__ float r1[256], r2[256];
    r1[t] = cs; r2[t] = bw;
    __syncthreads();
    for (int o = 128; o > 0; o >>= 1) {
        if (t < o) { r1[t] += r1[t + o]; r2[t] += r2[t + o]; }
        __syncthreads();
    }
    if (t == 0) { g_colsum[n] = r1[0]; g_bw[n] = r2[0]; }
}

// ===== K1: per-row mean/rstd + passthrough copy =====
__global__ void rowstats_copy_kernel(const float* __restrict__ X, float* __restrict__ outX) {
    int row = blockIdx.x;
    int t = threadIdx.x;          // 256, one float4 each
    float4 v = ((const float4*)X)[(size_t)row * 256 + t];
    ((float4*)outX)[(size_t)row * 256 + t] = v;
    float s = v.x + v.y + v.z + v.w;
    float q = v.x * v.x + v.y * v.y + v.z * v.z + v.w * v.w;
    for (int o = 16; o > 0; o >>= 1) {
        s += __shfl_down_sync(0xffffffffu, s, o);
        q += __shfl_down_sync(0xffffffffu, q, o);
    }
    __shared__ float wsm[8], wqm[8];
    if ((t & 31) == 0) { wsm[t >> 5] = s; wqm[t >> 5] = q; }
    __syncthreads();
    if (t == 0) {
        float S = 0.f, Q = 0.f;
        for (int i = 0; i < 8; i++) { S += wsm[i]; Q += wqm[i]; }
        float mu = S * (1.0f / HH);
        float var = Q * (1.0f / HH) - mu * mu;
        g_mu[row] = mu;
        g_rstd[row] = rsqrtf(var + 1e-5f);
    }
}

// ===================== K2: segment id per row + boundary positions =====================
__global__ void seg_kernel(const int* __restrict__ p) {
    int b = blockIdx.x;
    int t = threadIdx.x;          // 256 threads, 8 positions each
    const int* pb = p + b * LL;
    int base = t * 8;
    int cnt = 0;
#pragma unroll
    for (int i = 0; i < 8; i++) cnt += (pb[base + i] > 0);
    __shared__ int sc[256];
    sc[t] = cnt;
    __syncthreads();
    for (int o = 1; o < 256; o <<= 1) {
        int v = (t >= o) ? sc[t - o] : 0;
        __syncthreads();
        sc[t] += v;
        __syncthreads();
    }
    int k = (t > 0) ? sc[t - 1] : 0;  // exclusive prefix: boundaries before chunk
#pragma unroll
    for (int i = 0; i < 8; i++) {
        int pos = base + i;
        if (pb[pos] > 0) {
            if (k < SS) g_pi[b * SS + k] = pos;
            g_seg[b * LL + pos] = -1;     // boundary row excluded
            k++;
        } else {
            g_seg[b * LL + pos] = (k < SS) ? k : -1;
        }
    }
}

// ===================== K2b: zero the segment-sum accumulator (graph-replay safe) ==========
__global__ void zero_segsum_kernel() {
    int i = blockIdx.x * 256 + threadIdx.x;   // 65536 float4 = 262144 floats
    ((float4*)g_segsum)[i] = make_float4(0.f, 0.f, 0.f, 0.f);
}

// ===================== K3: tf32 mma.sync GEMM, 3-stage cp.async, 1 sync/K-tile =====
// A operand: raw fp32 bits fed to tf32 MMA (HW truncates to top 19 bits).
#define STAGES   3
#define A_STRIDE 36
#define B_STRIDE 132
#define STAGE_FLOATS (128 * A_STRIDE + 32 * B_STRIDE)
#define SMEM_FLOATS (STAGES * STAGE_FLOATS)
#define SMEM_BYTES  (SMEM_FLOATS * 4)          // 105984 bytes

__global__ void __launch_bounds__(256, 2) gemm_kernel(const float* __restrict__ X) {
    extern __shared__ float smem[];
    float (*As)[128][A_STRIDE] = (float (*)[128][A_STRIDE])smem;
    float (*Bs)[32][B_STRIDE]  = (float (*)[32][B_STRIDE])(smem + STAGES * 128 * A_STRIDE);

    int tid = threadIdx.x;
    int lane = tid & 31, wid = tid >> 5;
    int wm = wid & 1, wn = wid >> 1;       // 2 warps (M) x 4 warps (N)
    int bm = blockIdx.y * 128;
    int bn = blockIdx.x * 128;

    // per-thread load coordinates (fixed across tiles)
    int a_row = tid >> 3;            // 0..31 (stepped by 32 over pss)
    int a_col = (tid & 7) * 4;       // 0,4,...,28
    int b_kr  = tid >> 5;            // 0..7 (stepped by 8 over pss)
    int b_nc  = (tid & 31) * 4;      // 0..124

    const float* a_base = X + (size_t)(bm + a_row) * HH + a_col;
    const float* b_base = g_Wc + (size_t)b_kr * NN + bn + b_nc;

    float c[4][4][4];
#pragma unroll
    for (int i = 0; i < 4; i++)
#pragma unroll
        for (int j = 0; j < 4; j++)
#pragma unroll
            for (int r = 0; r < 4; r++) c[i][j][r] = 0.f;

#define LOAD_TILE(KT, BUF)                                                          \
    do {                                                                            \
        _Pragma("unroll")                                                           \
        for (int pss = 0; pss < 4; pss++) {                                         \
            unsigned dst = (unsigned)__cvta_generic_to_shared(                      \
                &As[BUF][pss * 32 + a_row][a_col]);                                 \
            const float* src = a_base + (size_t)(pss * 32) * HH + (KT);             \
            asm volatile("cp.async.cg.shared.global [%0], [%1], 16;"                \
                         :: "r"(dst), "l"(src) : "memory");                         \
        }                                                                           \
        _Pragma("unroll")                                                           \
        for (int pss = 0; pss < 4; pss++) {                                         \
            unsigned dst = (unsigned)__cvta_generic_to_shared(                      \
                &Bs[BUF][pss * 8 + b_kr][b_nc]);                                    \
            const float* src = b_base + (size_t)((KT) + pss * 8) * NN;              \
            asm volatile("cp.async.cg.shared.global [%0], [%1], 16;"                \
                         :: "r"(dst), "l"(src) : "memory");                         \
        }                                                                           \
        asm volatile("cp.async.commit_group;" ::: "memory");                        \
    } while (0)

    LOAD_TILE(0, 0);
    LOAD_TILE(32, 1);

    int buf = 0;       // stage holding tile kt
    int nld = 2;       // stage to load tile kt+2 into
    for (int kt = 0; kt < 32; kt++) {
        // ensure tile kt has landed (keep ≤1 newer group in flight)
        if (kt < 31)
            asm volatile("cp.async.wait_group 1;" ::: "memory");
        else
            asm volatile("cp.async.wait_group 0;" ::: "memory");
        __syncthreads();   // tile kt visible to all; all warps done with stage `nld`

        if (kt + 2 < 32) {
            LOAD_TILE((kt + 2) * 32, nld);
            if (++nld == STAGES) nld = 0;
        }

        const float (*A)[A_STRIDE] = As[buf];
        const float (*Bc)[B_STRIDE] = Bs[buf];
#pragma unroll
        for (int kk = 0; kk < 4; kk++) {
            int k0 = kk * 8 + (lane & 3);
            unsigned a[4][4];
#pragma unroll
            for (int mf = 0; mf < 4; mf++) {
                int r0 = wm * 64 + mf * 16 + (lane >> 2);
                a[mf][0] = __float_as_uint(A[r0][k0]);
                a[mf][1] = __float_as_uint(A[r0 + 8][k0]);
                a[mf][2] = __float_as_uint(A[r0][k0 + 4]);
                a[mf][3] = __float_as_uint(A[r0 + 8][k0 + 4]);
            }
            unsigned bf[4][2];
#pragma unroll
            for (int nf = 0; nf < 4; nf++) {
                int n0 = wn * 32 + nf * 8 + (lane >> 2);
                bf[nf][0] = __float_as_uint(Bc[k0][n0]);
                bf[nf][1] = __float_as_uint(Bc[k0 + 4][n0]);
            }
#pragma unroll
            for (int mf = 0; mf < 4; mf++)
#pragma unroll
                for (int nf = 0; nf < 4; nf++)
                    asm("mma.sync.aligned.m16n8k8.row.col.f32.tf32.tf32.f32 "
                        "{%0,%1,%2,%3}, {%4,%5,%6,%7}, {%8,%9}, {%0,%1,%2,%3};"
                        : "+f"(c[mf][nf][0]), "+f"(c[mf][nf][1]),
                          "+f"(c[mf][nf][2]), "+f"(c[mf][nf][3])
                        : "r"(a[mf][0]), "r"(a[mf][1]), "r"(a[mf][2]), "r"(a[mf][3]),
                          "r"(bf[nf][0]), "r"(bf[nf][1]));
        }
        if (++buf == STAGES) buf = 0;
    }

    // ---- fused epilogue: per-row LN affine + exact GELU + segmented atomic sums ----
    int bseg = (bm / LL) * SS;
    int rbase = bm + wm * 64 + (lane >> 2);
    float rrs[8], rmm[8];   // rstd, rstd*mu
    int   rsg[8];
#pragma unroll
    for (int i = 0; i < 8; i++) {
        int r = rbase + i * 8;
        float rs = g_rstd[r];
        rrs[i] = rs;
        rmm[i] = rs * g_mu[r];
        rsg[i] = g_seg[r];
    }
#pragma unroll
    for (int nf = 0; nf < 4; nf++) {
#pragma unroll
        for (int cs = 0; cs < 2; cs++) {
            int n = bn + wn * 32 + nf * 8 + (lane & 3) * 2 + cs;
            float csum = g_colsum[n];
            float bw   = g_bw[n];
            float acc = 0.f;
            int cur = -1;
#pragma unroll
            for (int i = 0; i < 8; i++) {
                int mf = i >> 1, sub = i & 1;
                int s = rsg[i];
                float cv = c[mf][nf][sub * 2 + cs];
                float val = fmaf(rrs[i], cv, fmaf(-rmm[i], csum, bw));
                val = 0.5f * val * (1.f + erff(val * 0.70710678118f));
                if (s >= 0) {
                    if (s != cur) {
                        if (cur >= 0) atomicAdd(&g_segsum[(bseg + cur) * NN + n], acc);
                        cur = s;
                        acc = 0.f;
                    }
                    acc += val;
                }
            }
            if (cur >= 0) atomicAdd(&g_segsum[(bseg + cur) * NN + n], acc);
        }
    }
#undef LOAD_TILE
}

// ===================== K5: per-batch tail (softmax, doc emb, final LN+GEMMs) =====================
__global__ void finalize_kernel(const float* __restrict__ as_s, const float* __restrict__ as_b,
                                const float* __restrict__ Wasp,
                                const float* __restrict__ se_s, const float* __restrict__ se_b,
                                const float* __restrict__ Wse,
                                float* __restrict__ out_result, float* __restrict__ out_asp) {
    int b = blockIdx.x;
    int t = threadIdx.x;          // 256
    __shared__ float docsum[NASP][256];
    __shared__ float wsum[NASP];
    __shared__ float red[512];    // [0..255]=sum tree, [256..511]=sumsq tree
    __shared__ float part[9][256];
    __shared__ float logits[9];
    __shared__ int   pis[SS];
    if (t < SS) pis[t] = g_pi[b * SS + t];
    if (t < NASP) wsum[t] = 0.f;
    for (int j = 0; j < NASP; j++) docsum[j][t] = 0.f;
    __syncthreads();

    for (int s = 0; s < SS; s++) {
        int end = pis[s];
        int start = (s == 0) ? 0 : (pis[s - 1] + 1);
        float inv_cnt = 1.0f / (float)(end - start);
        const float* seg = g_segsum + ((b * SS) + s) * NN;
        float aval = seg[t] * inv_cnt;
        float sval = seg[256 + t] * inv_cnt;
        // LN(a_sent) over 256
        red[t] = aval; red[256 + t] = aval * aval;
        __syncthreads();
        for (int o = 128; o > 0; o >>= 1) {
            if (t < o) { red[t] += red[t + o]; red[256 + t] += red[256 + t + o]; }
            __syncthreads();
        }
        float mu = red[0] * (1.0f / 256.f);
        float var = red[256] * (1.0f / 256.f) - mu * mu;
        float r = rsqrtf(var + 1e-5f);
        float ln = (aval - mu) * r * as_s[t] + as_b[t];
        for (int j = 0; j < 9; j++) part[j][t] = ln * Wasp[t * 9 + j];
        __syncthreads();
        for (int o = 128; o > 0; o >>= 1) {
            if (t < o) for (int j = 0; j < 9; j++) part[j][t] += part[j][t + o];
            __syncthreads();
        }
        if (t < 9) logits[t] = part[t][0];
        __syncthreads();
        float mx = -1e30f;
        for (int j = 0; j < 9; j++) mx = fmaxf(mx, logits[j]);
        float ex[9]; float den = 0.f;
        for (int j = 0; j < 9; j++) { ex[j] = expf(logits[j] - mx); den += ex[j]; }
        float inv = 1.f / den;
        if (t < 9) out_asp[(b * SS + s) * 9 + t] = ex[t] * inv;
        for (int j = 0; j < NASP; j++) docsum[j][t] += (ex[j] * inv) * sval;
        if (t == 0) for (int j = 0; j < NASP; j++) wsum[j] += ex[j] * inv;
        __syncthreads();
    }

    for (int j = 0; j < NASP; j++) {
        float emb = docsum[j][t] / wsum[j];
        red[t] = emb; red[256 + t] = emb * emb;
        __syncthreads();
        for (int o = 128; o > 0; o >>= 1) {
            if (t < o) { red[t] += red[t + o]; red[256 + t] += red[256 + t + o]; }
            __syncthreads();
        }
        float mu = red[0] * (1.0f / 256.f);
        float var = red[256] * (1.0f / 256.f) - mu * mu;
        float r = rsqrtf(var + 1e-5f);
        float ln = (emb - mu) * r * se_s[t] + se_b[t];
        for (int q = 0; q < NRAT; q++) part[q][t] = ln * Wse[t * NRAT + q];
        __syncthreads();
        for (int o = 128; o > 0; o >>= 1) {
            if (t < o) for (int q = 0; q < NRAT; q++) part[q][t] += part[q][t + o];
            __syncthreads();
        }
        if (t < NRAT) out_result[(b * NASP + j) * NRAT + t] = part[t][0];
        __syncthreads();
    }
}

// ===================== launch =====================
extern "C" void kernel_launch(void* const* d_in, const int* in_sizes, int n_in,
                              void* d_out, int out_size) {
    const float* X       = (const float*)d_in[0];
    const int*   p_index = (const int*)d_in[2];
    // n_sent may appear as a 1-element int input at index 3; params follow
    int base = (in_sizes[3] == 1) ? 4 : 3;
    const float* ln_a_s  = (const float*)d_in[base + 0];
    const float* ln_a_b  = (const float*)d_in[base + 1];
    const float* W_a     = (const float*)d_in[base + 2];
    const float* ln_s_s  = (const float*)d_in[base + 3];
    const float* ln_s_b  = (const float*)d_in[base + 4];
    const float* W_s     = (const float*)d_in[base + 5];
    const float* ln_asp_s= (const float*)d_in[base + 6];
    const float* ln_asp_b= (const float*)d_in[base + 7];
    const float* W_asp   = (const float*)d_in[base + 8];
    const float* ln_se_s = (const float*)d_in[base + 9];
    const float* ln_se_b = (const float*)d_in[base + 10];
    const float* W_se    = (const float*)d_in[base + 11];

    float* out        = (float*)d_out;
    float* out_result = out + OFF_RESULT;
    float* out_X      = out + OFF_X;
    float* out_asp    = out + OFF_ASP;

    static int smem_set = 0;
    if (!smem_set) {
        cudaFuncSetAttribute(gemm_kernel, cudaFuncAttributeMaxDynamicSharedMemorySize,
                             SMEM_BYTES);
        smem_set = 1;
    }

    prep_kernel<<<NN, 256>>>(W_a, W_s, ln_a_s, ln_a_b, ln_s_s, ln_s_b);
    seg_kernel<<<BB, 256>>>(p_index);
    zero_segsum_kernel<<<256, 256>>>();
    rowstats_copy_kernel<<<MM, 256>>>(X, out_X);
    dim3 g3(NN / 128, MM / 128);        // (4, 256)
    gemm_kernel<<<g3, 256, SMEM_BYTES>>>(X);
    finalize_kernel<<<BB, 256>>>(ln_asp_s, ln_asp_b, W_asp, ln_se_s, ln_se_b, W_se,
                                 out_result, out_asp);
}

// round 17
// speedup vs baseline: 1.1864x; 1.0025x over previous
#include <cuda_runtime.h>
#include <math.h>
#include <stdint.h>

// Problem constants (fixed shapes)
#define BB   16
#define LL   2048
#define HH   1024
#define SS   32
#define PP   256
#define NN   512            // 2*P combined GEMM width (a | s)
#define MM   (BB*LL)        // 32768 rows
#define NASP 8
#define NRAT 5

// Output layout: (result[B,8,5], outputs[B,L,H], aspect_doc[B,32,9]) flattened
#define OFF_RESULT 0
#define OFF_X      640
#define OFF_ASP    (640 + BB*LL*HH)

// -------- device scratch (static; no runtime allocation allowed) --------
__device__ float g_Wc[HH * NN];            // folded, tf32-rounded weights (k-major)
__device__ float g_colsum[NN];             // sum_h s_h*W[h,n]
__device__ float g_bw[NN];                 // sum_h b_h*W[h,n]
__device__ float g_mu[MM];
__device__ float g_rstd[MM];
__device__ int   g_seg[MM];                // segment id per row, -1 = excluded
__device__ int   g_pi[BB * SS];            // boundary positions
__device__ float g_segsum[BB * SS * NN];

// ===================== K0: fold LN scale/bias into weights =====================
__global__ void prep_kernel(const float* __restrict__ Wa, const float* __restrict__ Ws,
                            const float* __restrict__ sa, const float* __restrict__ ba,
                            const float* __restrict__ ss, const float* __restrict__ bs) {
    int n = blockIdx.x;           // 0..511
    int t = threadIdx.x;          // 256
    bool isA = (n < PP);
    const float* W  = isA ? Wa : Ws;
    const float* sv = isA ? sa : ss;
    const float* bv = isA ? ba : bs;
    int nc = isA ? n : (n - PP);
    float cs = 0.f, bw = 0.f;
    for (int k = t; k < HH; k += 256) {
        float w = W[k * PP + nc];
        float f = sv[k] * w;
        unsigned u;
        asm("cvt.rna.tf32.f32 %0, %1;" : "=r"(u) : "f"(f));
        g_Wc[k * NN + n] = __uint_as_float(u);
        cs += f;
        bw += bv[k] * w;
    }
    __shared__ float r1[256], r2[256];
    r1[t] = cs; r2[t] = bw;
    __syncthreads();
    for (int o = 128; o > 0; o >>= 1) {
        if (t < o) { r1[t] += r1[t + o]; r2[t] += r2[t + o]; }
        __syncthreads();
    }
    if (t == 0) { g_colsum[n] = r1[0]; g_bw[n] = r2[0]; }
}

// ===== K1: per-row mean/rstd + passthrough copy =====
__global__ void rowstats_copy_kernel(const float* __restrict__ X, float* __restrict__ outX) {
    int row = blockIdx.x;
    int t = threadIdx.x;          // 256, one float4 each
    float4 v = ((const float4*)X)[(size_t)row * 256 + t];
    ((float4*)outX)[(size_t)row * 256 + t] = v;
    float s = v.x + v.y + v.z + v.w;
    float q = v.x * v.x + v.y * v.y + v.z * v.z + v.w * v.w;
    for (int o = 16; o > 0; o >>= 1) {
        s += __shfl_down_sync(0xffffffffu, s, o);
        q += __shfl_down_sync(0xffffffffu, q, o);
    }
    __shared__ float wsm[8], wqm[8];
    if ((t & 31) == 0) { wsm[t >> 5] = s; wqm[t >> 5] = q; }
    __syncthreads();
    if (t == 0) {
        float S = 0.f, Q = 0.f;
        for (int i = 0; i < 8; i++) { S += wsm[i]; Q += wqm[i]; }
        float mu = S * (1.0f / HH);
        float var = Q * (1.0f / HH) - mu * mu;
        g_mu[row] = mu;
        g_rstd[row] = rsqrtf(var + 1e-5f);
    }
}

// ===================== K2: segment id per row + boundary positions =====================
__global__ void seg_kernel(const int* __restrict__ p) {
    int b = blockIdx.x;
    int t = threadIdx.x;          // 256 threads, 8 positions each
    const int* pb = p + b * LL;
    int base = t * 8;
    int cnt = 0;
#pragma unroll
    for (int i = 0; i < 8; i++) cnt += (pb[base + i] > 0);
    __shared__ int sc[256];
    sc[t] = cnt;
    __syncthreads();
    for (int o = 1; o < 256; o <<= 1) {
        int v = (t >= o) ? sc[t - o] : 0;
        __syncthreads();
        sc[t] += v;
        __syncthreads();
    }
    int k = (t > 0) ? sc[t - 1] : 0;  // exclusive prefix: boundaries before chunk
#pragma unroll
    for (int i = 0; i < 8; i++) {
        int pos = base + i;
        if (pb[pos] > 0) {
            if (k < SS) g_pi[b * SS + k] = pos;
            g_seg[b * LL + pos] = -1;     // boundary row excluded
            k++;
        } else {
            g_seg[b * LL + pos] = (k < SS) ? k : -1;
        }
    }
}

// ===================== K2b: zero the segment-sum accumulator (graph-replay safe) ==========
__global__ void zero_segsum_kernel() {
    int i = blockIdx.x * 256 + threadIdx.x;   // 65536 float4 = 262144 floats
    ((float4*)g_segsum)[i] = make_float4(0.f, 0.f, 0.f, 0.f);
}

// ===================== K3: tf32 mma.sync GEMM, 3-stage cp.async, 1 sync/K-tile =====
// A operand: raw fp32 bits fed to tf32 MMA (HW truncates to top 19 bits).
#define STAGES   3
#define A_STRIDE 36
#define B_STRIDE 132
#define STAGE_FLOATS (128 * A_STRIDE + 32 * B_STRIDE)
#define SMEM_FLOATS (STAGES * STAGE_FLOATS)
#define SMEM_BYTES  (SMEM_FLOATS * 4)          // 105984 bytes

__global__ void __launch_bounds__(256, 2) gemm_kernel(const float* __restrict__ X) {
    extern __shared__ float smem[];
    float (*As)[128][A_STRIDE] = (float (*)[128][A_STRIDE])smem;
    float (*Bs)[32][B_STRIDE]  = (float (*)[32][B_STRIDE])(smem + STAGES * 128 * A_STRIDE);

    int tid = threadIdx.x;
    int lane = tid & 31, wid = tid >> 5;
    int wm = wid & 1, wn = wid >> 1;       // 2 warps (M) x 4 warps (N)
    int bm = blockIdx.y * 128;
    int bn = blockIdx.x * 128;

    // per-thread load coordinates (fixed across tiles)
    int a_row = tid >> 3;            // 0..31 (stepped by 32 over pss)
    int a_col = (tid & 7) * 4;       // 0,4,...,28
    int b_kr  = tid >> 5;            // 0..7 (stepped by 8 over pss)
    int b_nc  = (tid & 31) * 4;      // 0..124

    const float* a_base = X + (size_t)(bm + a_row) * HH + a_col;
    const float* b_base = g_Wc + (size_t)b_kr * NN + bn + b_nc;

    float c[4][4][4];
#pragma unroll
    for (int i = 0; i < 4; i++)
#pragma unroll
        for (int j = 0; j < 4; j++)
#pragma unroll
            for (int r = 0; r < 4; r++) c[i][j][r] = 0.f;

#define LOAD_TILE(KT, BUF)                                                          \
    do {                                                                            \
        _Pragma("unroll")                                                           \
        for (int pss = 0; pss < 4; pss++) {                                         \
            unsigned dst = (unsigned)__cvta_generic_to_shared(                      \
                &As[BUF][pss * 32 + a_row][a_col]);                                 \
            const float* src = a_base + (size_t)(pss * 32) * HH + (KT);             \
            asm volatile("cp.async.cg.shared.global [%0], [%1], 16;"                \
                         :: "r"(dst), "l"(src) : "memory");                         \
        }                                                                           \
        _Pragma("unroll")                                                           \
        for (int pss = 0; pss < 4; pss++) {                                         \
            unsigned dst = (unsigned)__cvta_generic_to_shared(                      \
                &Bs[BUF][pss * 8 + b_kr][b_nc]);                                    \
            const float* src = b_base + (size_t)((KT) + pss * 8) * NN;              \
            asm volatile("cp.async.cg.shared.global [%0], [%1], 16;"                \
                         :: "r"(dst), "l"(src) : "memory");                         \
        }                                                                           \
        asm volatile("cp.async.commit_group;" ::: "memory");                        \
    } while (0)

    LOAD_TILE(0, 0);
    LOAD_TILE(32, 1);

    int buf = 0;       // stage holding tile kt
    int nld = 2;       // stage to load tile kt+2 into
    for (int kt = 0; kt < 32; kt++) {
        // ensure tile kt has landed (keep ≤1 newer group in flight)
        if (kt < 31)
            asm volatile("cp.async.wait_group 1;" ::: "memory");
        else
            asm volatile("cp.async.wait_group 0;" ::: "memory");
        __syncthreads();   // tile kt visible to all; all warps done with stage `nld`

        if (kt + 2 < 32) {
            LOAD_TILE((kt + 2) * 32, nld);
            if (++nld == STAGES) nld = 0;
        }

        const float (*A)[A_STRIDE] = As[buf];
        const float (*Bc)[B_STRIDE] = Bs[buf];
#pragma unroll
        for (int kk = 0; kk < 4; kk++) {
            int k0 = kk * 8 + (lane & 3);
            unsigned a[4][4];
#pragma unroll
            for (int mf = 0; mf < 4; mf++) {
                int r0 = wm * 64 + mf * 16 + (lane >> 2);
                a[mf][0] = __float_as_uint(A[r0][k0]);
                a[mf][1] = __float_as_uint(A[r0 + 8][k0]);
                a[mf][2] = __float_as_uint(A[r0][k0 + 4]);
                a[mf][3] = __float_as_uint(A[r0 + 8][k0 + 4]);
            }
            unsigned bf[4][2];
#pragma unroll
            for (int nf = 0; nf < 4; nf++) {
                int n0 = wn * 32 + nf * 8 + (lane >> 2);
                bf[nf][0] = __float_as_uint(Bc[k0][n0]);
                bf[nf][1] = __float_as_uint(Bc[k0 + 4][n0]);
            }
#pragma unroll
            for (int mf = 0; mf < 4; mf++)
#pragma unroll
                for (int nf = 0; nf < 4; nf++)
                    asm("mma.sync.aligned.m16n8k8.row.col.f32.tf32.tf32.f32 "
                        "{%0,%1,%2,%3}, {%4,%5,%6,%7}, {%8,%9}, {%0,%1,%2,%3};"
                        : "+f"(c[mf][nf][0]), "+f"(c[mf][nf][1]),
                          "+f"(c[mf][nf][2]), "+f"(c[mf][nf][3])
                        : "r"(a[mf][0]), "r"(a[mf][1]), "r"(a[mf][2]), "r"(a[mf][3]),
                          "r"(bf[nf][0]), "r"(bf[nf][1]));
        }
        if (++buf == STAGES) buf = 0;
    }

    // ---- fused epilogue: per-row LN affine + exact GELU + segmented atomic sums ----
    int bseg = (bm / LL) * SS;
    int rbase = bm + wm * 64 + (lane >> 2);
    float rrs[8], rmm[8];   // rstd, rstd*mu
    int   rsg[8];
#pragma unroll
    for (int i = 0; i < 8; i++) {
        int r = rbase + i * 8;
        float rs = g_rstd[r];
        rrs[i] = rs;
        rmm[i] = rs * g_mu[r];
        rsg[i] = g_seg[r];
    }
#pragma unroll
    for (int nf = 0; nf < 4; nf++) {
#pragma unroll
        for (int cs = 0; cs < 2; cs++) {
            int n = bn + wn * 32 + nf * 8 + (lane & 3) * 2 + cs;
            float csum = g_colsum[n];
            float bw   = g_bw[n];
            float acc = 0.f;
            int cur = -1;
#pragma unroll
            for (int i = 0; i < 8; i++) {
                int mf = i >> 1, sub = i & 1;
                int s = rsg[i];
                float cv = c[mf][nf][sub * 2 + cs];
                float val = fmaf(rrs[i], cv, fmaf(-rmm[i], csum, bw));
                val = 0.5f * val * (1.f + erff(val * 0.70710678118f));
                if (s >= 0) {
                    if (s != cur) {
                        if (cur >= 0) atomicAdd(&g_segsum[(bseg + cur) * NN + n], acc);
                        cur = s;
                        acc = 0.f;
                    }
                    acc += val;
                }
            }
            if (cur >= 0) atomicAdd(&g_segsum[(bseg + cur) * NN + n], acc);
        }
    }
#undef LOAD_TILE
}

// ===================== K5: per-batch tail (softmax, doc emb, final LN+GEMMs) =====================
__global__ void finalize_kernel(const float* __restrict__ as_s, const float* __restrict__ as_b,
                                const float* __restrict__ Wasp,
                                const float* __restrict__ se_s, const float* __restrict__ se_b,
                                const float* __restrict__ Wse,
                                float* __restrict__ out_result, float* __restrict__ out_asp) {
    int b = blockIdx.x;
    int t = threadIdx.x;          // 256
    __shared__ float docsum[NASP][256];
    __shared__ float wsum[NASP];
    __shared__ float red[512];    // [0..255]=sum tree, [256..511]=sumsq tree
    __shared__ float part[9][256];
    __shared__ float logits[9];
    __shared__ int   pis[SS];
    if (t < SS) pis[t] = g_pi[b * SS + t];
    if (t < NASP) wsum[t] = 0.f;
    for (int j = 0; j < NASP; j++) docsum[j][t] = 0.f;
    __syncthreads();

    for (int s = 0; s < SS; s++) {
        int end = pis[s];
        int start = (s == 0) ? 0 : (pis[s - 1] + 1);
        float inv_cnt = 1.0f / (float)(end - start);
        const float* seg = g_segsum + ((b * SS) + s) * NN;
        float aval = seg[t] * inv_cnt;
        float sval = seg[256 + t] * inv_cnt;
        // LN(a_sent) over 256
        red[t] = aval; red[256 + t] = aval * aval;
        __syncthreads();
        for (int o = 128; o > 0; o >>= 1) {
            if (t < o) { red[t] += red[t + o]; red[256 + t] += red[256 + t + o]; }
            __syncthreads();
        }
        float mu = red[0] * (1.0f / 256.f);
        float var = red[256] * (1.0f / 256.f) - mu * mu;
        float r = rsqrtf(var + 1e-5f);
        float ln = (aval - mu) * r * as_s[t] + as_b[t];
        for (int j = 0; j < 9; j++) part[j][t] = ln * Wasp[t * 9 + j];
        __syncthreads();
        for (int o = 128; o > 0; o >>= 1) {
            if (t < o) for (int j = 0; j < 9; j++) part[j][t] += part[j][t + o];
            __syncthreads();
        }
        if (t < 9) logits[t] = part[t][0];
        __syncthreads();
        float mx = -1e30f;
        for (int j = 0; j < 9; j++) mx = fmaxf(mx, logits[j]);
        float ex[9]; float den = 0.f;
        for (int j = 0; j < 9; j++) { ex[j] = expf(logits[j] - mx); den += ex[j]; }
        float inv = 1.f / den;
        if (t < 9) out_asp[(b * SS + s) * 9 + t] = ex[t] * inv;
        for (int j = 0; j < NASP; j++) docsum[j][t] += (ex[j] * inv) * sval;
        if (t == 0) for (int j = 0; j < NASP; j++) wsum[j] += ex[j] * inv;
        __syncthreads();
    }

    for (int j = 0; j < NASP; j++) {
        float emb = docsum[j][t] / wsum[j];
        red[t] = emb; red[256 + t] = emb * emb;
        __syncthreads();
        for (int o = 128; o > 0; o >>= 1) {
            if (t < o) { red[t] += red[t + o]; red[256 + t] += red[256 + t + o]; }
            __syncthreads();
        }
        float mu = red[0] * (1.0f / 256.f);
        float var = red[256] * (1.0f / 256.f) - mu * mu;
        float r = rsqrtf(var + 1e-5f);
        float ln = (emb - mu) * r * se_s[t] + se_b[t];
        for (int q = 0; q < NRAT; q++) part[q][t] = ln * Wse[t * NRAT + q];
        __syncthreads();
        for (int o = 128; o > 0; o >>= 1) {
            if (t < o) for (int q = 0; q < NRAT; q++) part[q][t] += part[q][t + o];
            __syncthreads();
        }
        if (t < NRAT) out_result[(b * NASP + j) * NRAT + t] = part[t][0];
        __syncthreads();
    }
}

// ===================== launch =====================
extern "C" void kernel_launch(void* const* d_in, const int* in_sizes, int n_in,
                              void* d_out, int out_size) {
    const float* X       = (const float*)d_in[0];
    const int*   p_index = (const int*)d_in[2];
    // n_sent may appear as a 1-element int input at index 3; params follow
    int base = (in_sizes[3] == 1) ? 4 : 3;
    const float* ln_a_s  = (const float*)d_in[base + 0];
    const float* ln_a_b  = (const float*)d_in[base + 1];
    const float* W_a     = (const float*)d_in[base + 2];
    const float* ln_s_s  = (const float*)d_in[base + 3];
    const float* ln_s_b  = (const float*)d_in[base + 4];
    const float* W_s     = (const float*)d_in[base + 5];
    const float* ln_asp_s= (const float*)d_in[base + 6];
    const float* ln_asp_b= (const float*)d_in[base + 7];
    const float* W_asp   = (const float*)d_in[base + 8];
    const float* ln_se_s = (const float*)d_in[base + 9];
    const float* ln_se_b = (const float*)d_in[base + 10];
    const float* W_se    = (const float*)d_in[base + 11];

    float* out        = (float*)d_out;
    float* out_result = out + OFF_RESULT;
    float* out_X      = out + OFF_X;
    float* out_asp    = out + OFF_ASP;

    static int smem_set = 0;
    if (!smem_set) {
        cudaFuncSetAttribute(gemm_kernel, cudaFuncAttributeMaxDynamicSharedMemorySize,
                             SMEM_BYTES);
        smem_set = 1;
    }

    prep_kernel<<<NN, 256>>>(W_a, W_s, ln_a_s, ln_a_b, ln_s_s, ln_s_b);
    seg_kernel<<<BB, 256>>>(p_index);
    zero_segsum_kernel<<<256, 256>>>();
    rowstats_copy_kernel<<<MM, 256>>>(X, out_X);
    dim3 g3(NN / 128, MM / 128);        // (4, 256)
    gemm_kernel<<<g3, 256, SMEM_BYTES>>>(X);
    finalize_kernel<<<BB, 256>>>(ln_asp_s, ln_asp_b, W_asp, ln_se_s, ln_se_b, W_se,
                                 out_result, out_asp);
}